// round 9
// baseline (speedup 1.0000x reference)
#include <cuda_runtime.h>
#include <math.h>
#include <stdint.h>

// Problem constants
#define CC    256
#define NTOK  98          // tokens per window (2*7*7)
#define NHD   8
#define NPT   4
#define HDIM  32
#define NWIN  512
#define TOT   (NWIN*NTOK) // 50176 tokens
#define HHH   56
#define WWIDE 56

// ---------------- scratch (static device globals; no allocation) ----------------
__device__ float g_bufA[(size_t)TOT*CC];   // xw  (post-LN1, window order)
__device__ float g_bufB[(size_t)TOT*CC];   // q   / later LN2 output
__device__ float g_bufC[(size_t)TOT*CC];   // value
__device__ float g_bufD[(size_t)TOT*CC];   // attn vector (pre out_w)
__device__ float g_bufE[(size_t)TOT*CC];   // attn out / post-LN
__device__ float g_offb[(size_t)TOT*96];   // offsets
__device__ float g_awb [(size_t)TOT*32];   // attention weights (logits -> softmax)
__device__ float g_hb  [(size_t)TOT*1024]; // fc1 hidden

// ---------------- helpers ----------------
__device__ __forceinline__ float block_reduce_256(float v, float* sh)
{
    #pragma unroll
    for (int o = 16; o > 0; o >>= 1) v += __shfl_down_sync(0xffffffffu, v, o);
    int lane = threadIdx.x & 31, wid = threadIdx.x >> 5;
    if (lane == 0) sh[wid] = v;
    __syncthreads();
    if (wid == 0) {
        v = (lane < 8) ? sh[lane] : 0.f;
        #pragma unroll
        for (int o = 4; o > 0; o >>= 1) v += __shfl_down_sync(0xffffffffu, v, o);
        if (lane == 0) sh[0] = v;
    }
    __syncthreads();
    float r = sh[0];
    __syncthreads();
    return r;
}

__device__ __forceinline__ float gelu_f(float x)
{
    float x3 = x * x * x;
    return 0.5f * x * (1.f + tanhf(0.7978845608028654f * (x + 0.044715f * x3)));
}

// ---------------- stage 1: LN1 + window partition + positional diag -> xw, q ----
__global__ void k_ln1diag(const float* __restrict__ x, const float* __restrict__ mask,
                          const float* __restrict__ g1, const float* __restrict__ b1)
{
    __shared__ float sh[8];
    __shared__ float sdiag;
    int t = blockIdx.x;
    int win = t / NTOK, n = t % NTOK;
    int dwn = win >> 6, hwn = (win >> 3) & 7, wwn = win & 7;
    int wd = n / 49, rm = n % 49, wh = rm / 7, wx = rm % 7;
    int d = dwn * 2 + wd, h = hwn * 7 + wh, w = wwn * 7 + wx;
    size_t g = ((size_t)d * HHH + h) * WWIDE + w;
    int c = threadIdx.x;

    float v = x[g * CC + c];
    float mean = block_reduce_256(v, sh) * (1.f / 256.f);
    float dv = v - mean;
    float var = block_reduce_256(dv * dv, sh) * (1.f / 256.f);
    float xn = dv * rsqrtf(var + 1e-5f) * g1[c] + b1[c];

    if (c == 0) {
        const float* mrow = mask + ((size_t)win * NTOK + n) * NTOK; // z*49+y*7+x layout
        float m = mrow[(wd * 7 + wh) * 7 + wx];
        float zs = 0.f, ys = 0.f, xs = 0.f;
        for (int z = 0; z <= wd; z++) zs += mrow[z * 49 + wh * 7 + wx];
        for (int y = 0; y <= wh; y++) ys += mrow[wd * 49 + y * 7 + wx];
        for (int xq = 0; xq <= wx; xq++) xs += mrow[wd * 49 + wh * 7 + xq];
        const float INV_PI = 0.3183098861837907f;
        const float PI_F   = 3.14159265358979323846f;
        float x_e = xs * m * INV_PI;
        float y_e = ys * m * INV_PI;
        float z_e = zs * m * INV_PI;
        sdiag = m * (sinf(x_e) + sinf(PI_F * y_e) + z_e);
    }
    __syncthreads();
    float diag = sdiag;
    g_bufA[(size_t)t * CC + c] = xn;
    g_bufB[(size_t)t * CC + c] = xn + diag;
}

// ---------------- generic tiled SGEMM: out = A[M,K] @ W[K,N] + bias -------------
// mode 0: plain store  (out[r*N+col])
// mode 1: gelu store
// mode 2: window-reverse + residual:  out[g*256+col] = aux[g*256+col] + v  (N==256)
// mode 3: residual add: out[r*N+col] = aux[r*N+col] + v
__global__ void k_gemm(const float* __restrict__ A, const float* __restrict__ W,
                       const float* __restrict__ bias, float* __restrict__ out,
                       int K, int N, int mode, const float* __restrict__ aux)
{
    __shared__ float As[16][64];
    __shared__ float Bs[16][64];
    int n0   = blockIdx.x * 64;
    int row0 = blockIdx.y * 64;
    int tid = threadIdx.x;
    int tx = tid & 15, ty = tid >> 4;

    int lr = tid >> 2;          // A loader: row 0..63
    int lk = (tid & 3) * 4;     // A loader: k sub-offset
    int bk = tid >> 4;          // B loader: k row 0..15
    int bc = (tid & 15) * 4;    // B loader: col 0..60

    float acc[4][4];
    #pragma unroll
    for (int i = 0; i < 4; i++)
        #pragma unroll
        for (int j = 0; j < 4; j++) acc[i][j] = 0.f;

    for (int k0 = 0; k0 < K; k0 += 16) {
        float4 a4 = *(const float4*)(A + (size_t)(row0 + lr) * K + k0 + lk);
        As[lk + 0][lr] = a4.x; As[lk + 1][lr] = a4.y;
        As[lk + 2][lr] = a4.z; As[lk + 3][lr] = a4.w;

        float4 b4;
        if (n0 + bc < N) b4 = *(const float4*)(W + (size_t)(k0 + bk) * N + n0 + bc);
        else             b4 = make_float4(0.f, 0.f, 0.f, 0.f);
        *(float4*)&Bs[bk][bc] = b4;
        __syncthreads();

        #pragma unroll
        for (int kk = 0; kk < 16; kk++) {
            float4 a = *(const float4*)&As[kk][ty * 4];
            float4 b = *(const float4*)&Bs[kk][tx * 4];
            acc[0][0] += a.x * b.x; acc[0][1] += a.x * b.y; acc[0][2] += a.x * b.z; acc[0][3] += a.x * b.w;
            acc[1][0] += a.y * b.x; acc[1][1] += a.y * b.y; acc[1][2] += a.y * b.z; acc[1][3] += a.y * b.w;
            acc[2][0] += a.z * b.x; acc[2][1] += a.z * b.y; acc[2][2] += a.z * b.z; acc[2][3] += a.z * b.w;
            acc[3][0] += a.w * b.x; acc[3][1] += a.w * b.y; acc[3][2] += a.w * b.z; acc[3][3] += a.w * b.w;
        }
        __syncthreads();
    }

    #pragma unroll
    for (int i = 0; i < 4; i++) {
        int r = row0 + ty * 4 + i;
        size_t gidx = 0;
        if (mode == 2) {
            int win = r / NTOK, n = r % NTOK;
            int dwn = win >> 6, hwn = (win >> 3) & 7, wwn = win & 7;
            int wd = n / 49, rm = n % 49, wh = rm / 7, wx = rm % 7;
            gidx = ((size_t)(dwn * 2 + wd) * HHH + (hwn * 7 + wh)) * WWIDE + (wwn * 7 + wx);
        }
        #pragma unroll
        for (int j = 0; j < 4; j++) {
            int col = n0 + tx * 4 + j;
            if (col < N) {
                float v = acc[i][j] + bias[col];
                if (mode == 0)      out[(size_t)r * N + col] = v;
                else if (mode == 1) out[(size_t)r * N + col] = gelu_f(v);
                else if (mode == 2) out[gidx * 256 + col] = aux[gidx * 256 + col] + v;
                else                out[(size_t)r * N + col] = aux[(size_t)r * N + col] + v;
            }
        }
    }
}

// ---------------- softmax over NP=4 -------------------------------------------
__global__ void k_softmax4(float* __restrict__ a)
{
    int i = blockIdx.x * blockDim.x + threadIdx.x;
    if (i >= TOT * NHD) return;
    float* p = a + (size_t)i * 4;
    float l0 = p[0], l1 = p[1], l2 = p[2], l3 = p[3];
    float m = fmaxf(fmaxf(l0, l1), fmaxf(l2, l3));
    float e0 = __expf(l0 - m), e1 = __expf(l1 - m), e2 = __expf(l2 - m), e3 = __expf(l3 - m);
    float inv = 1.f / (e0 + e1 + e2 + e3);
    p[0] = e0 * inv; p[1] = e1 * inv; p[2] = e2 * inv; p[3] = e3 * inv;
}

// ---------------- deformable trilinear sampling per (window, head) --------------
__global__ void k_sample()
{
    __shared__ float sval[NTOK * HDIM];   // 12.25 KB
    int win  = blockIdx.x >> 3;
    int head = blockIdx.x & 7;

    for (int i = threadIdx.x; i < NTOK * HDIM; i += 256) {
        int s = i >> 5, dch = i & 31;
        sval[i] = g_bufC[((size_t)win * NTOK + s) * CC + head * HDIM + dch];
    }
    __syncthreads();

    int warp = threadIdx.x >> 5, lane = threadIdx.x & 31;
    for (int nn = warp; nn < NTOK; nn += 8) {
        int t = win * NTOK + nn;
        int z = nn / 49, rm = nn % 49, y = rm / 7, xq = rm % 7;
        float rx = (xq + 0.5f) / 7.0f;
        float ry = (y  + 0.5f) / 7.0f;
        float rz = (z  + 0.5f) / 2.0f;
        const float* offp = g_offb + (size_t)t * 96 + head * 12;
        const float* awp  = g_awb  + (size_t)t * 32 + head * 4;
        float tot = 0.f;
        #pragma unroll
        for (int p = 0; p < 4; p++) {
            float ox = offp[p * 3 + 0], oy = offp[p * 3 + 1], oz = offp[p * 3 + 2];
            float aw = awp[p];
            float px = (rx + ox * (1.f / 7.f)) * 7.f - 0.5f;
            float py = (ry + oy * (1.f / 7.f)) * 7.f - 0.5f;
            float pz = (rz + oz * (1.f / 2.f)) * 2.f - 0.5f;
            float x0 = floorf(px), y0 = floorf(py), z0 = floorf(pz);
            float samp = 0.f;
            #pragma unroll
            for (int dz = 0; dz < 2; dz++)
            #pragma unroll
            for (int dy = 0; dy < 2; dy++)
            #pragma unroll
            for (int dx = 0; dx < 2; dx++) {
                float xi = x0 + dx, yi = y0 + dy, zi = z0 + dz;
                float wgt = (1.f - fabsf(px - xi)) * (1.f - fabsf(py - yi)) * (1.f - fabsf(pz - zi));
                bool valid = (xi >= 0.f) && (xi < 7.f) && (yi >= 0.f) && (yi < 7.f) &&
                             (zi >= 0.f) && (zi < 2.f);
                if (valid) {
                    int idx = (((int)zi) * 7 + (int)yi) * 7 + (int)xi;
                    samp += wgt * sval[idx * HDIM + lane];
                }
            }
            tot += aw * samp;
        }
        g_bufD[(size_t)t * CC + head * HDIM + lane] = tot;
    }
}

// ---------------- residual + LN (anorm), window order ---------------------------
__global__ void k_addln(const float* __restrict__ gg, const float* __restrict__ bb)
{
    __shared__ float sh[8];
    int t = blockIdx.x, c = threadIdx.x;
    float v = g_bufA[(size_t)t * CC + c] + g_bufE[(size_t)t * CC + c];
    float mean = block_reduce_256(v, sh) * (1.f / 256.f);
    float dv = v - mean;
    float var = block_reduce_256(dv * dv, sh) * (1.f / 256.f);
    g_bufE[(size_t)t * CC + c] = dv * rsqrtf(var + 1e-5f) * gg[c] + bb[c];
}

// ---------------- LN2 over the (B,D,H,W,C) residual stream ---------------------
__global__ void k_ln2(const float* __restrict__ xin,
                      const float* __restrict__ gg, const float* __restrict__ bb)
{
    __shared__ float sh[8];
    int t = blockIdx.x, c = threadIdx.x;
    float v = xin[(size_t)t * CC + c];
    float mean = block_reduce_256(v, sh) * (1.f / 256.f);
    float dv = v - mean;
    float var = block_reduce_256(dv * dv, sh) * (1.f / 256.f);
    g_bufB[(size_t)t * CC + c] = dv * rsqrtf(var + 1e-5f) * gg[c] + bb[c];
}

// ---------------- launch --------------------------------------------------------
extern "C" void kernel_launch(void* const* d_in, const int* in_sizes, int n_in,
                              void* d_out, int out_size)
{
    (void)in_sizes; (void)n_in; (void)out_size;
    const float* x     = (const float*)d_in[0];
    const float* mask  = (const float*)d_in[1];
    const float* n1g   = (const float*)d_in[2];
    const float* n1b   = (const float*)d_in[3];
    const float* valw  = (const float*)d_in[4];
    const float* valb  = (const float*)d_in[5];
    const float* offw  = (const float*)d_in[6];
    const float* offbi = (const float*)d_in[7];
    const float* aww   = (const float*)d_in[8];
    const float* awbi  = (const float*)d_in[9];
    const float* outw  = (const float*)d_in[10];
    const float* outbi = (const float*)d_in[11];
    const float* ang   = (const float*)d_in[12];
    const float* anb   = (const float*)d_in[13];
    const float* projw = (const float*)d_in[14];
    const float* projb = (const float*)d_in[15];
    const float* n2g   = (const float*)d_in[16];
    const float* n2b   = (const float*)d_in[17];
    const float* fc1w  = (const float*)d_in[18];
    const float* fc1b  = (const float*)d_in[19];
    const float* fc2w  = (const float*)d_in[20];
    const float* fc2b  = (const float*)d_in[21];
    float* out = (float*)d_out;

    float *pA, *pB, *pC, *pD, *pE, *pOff, *pAw, *pH;
    cudaGetSymbolAddress((void**)&pA, g_bufA);
    cudaGetSymbolAddress((void**)&pB, g_bufB);
    cudaGetSymbolAddress((void**)&pC, g_bufC);
    cudaGetSymbolAddress((void**)&pD, g_bufD);
    cudaGetSymbolAddress((void**)&pE, g_bufE);
    cudaGetSymbolAddress((void**)&pOff, g_offb);
    cudaGetSymbolAddress((void**)&pAw,  g_awb);
    cudaGetSymbolAddress((void**)&pH,   g_hb);

    const int MT = TOT / 64;  // 784 row tiles

    // 1. LN1 + partition + diag -> xw (A), q (B)
    k_ln1diag<<<TOT, 256>>>(x, mask, n1g, n1b);
    // 2. value = xw @ val_w + b
    k_gemm<<<dim3(4, MT), 256>>>(pA, valw, valb, pC, 256, 256, 0, nullptr);
    // 3. off = q @ off_w + b ; aw logits = q @ aw_w + b
    k_gemm<<<dim3(2, MT), 256>>>(pB, offw, offbi, pOff, 256, 96, 0, nullptr);
    k_gemm<<<dim3(1, MT), 256>>>(pB, aww, awbi, pAw, 256, 32, 0, nullptr);
    // 4. softmax over NP
    k_softmax4<<<(TOT * NHD + 255) / 256, 256>>>(pAw);
    // 5. deformable trilinear sampling -> attn vector (D)
    k_sample<<<NWIN * NHD, 256>>>();
    // 6. attn out = D @ out_w + b -> E
    k_gemm<<<dim3(4, MT), 256>>>(pD, outw, outbi, pE, 256, 256, 0, nullptr);
    // 7. E = LN(xw + E) with anorm
    k_addln<<<TOT, 256>>>(ang, anb);
    // 8. window-reverse + residual: out = x + (E @ proj_w + b)
    k_gemm<<<dim3(4, MT), 256>>>(pE, projw, projb, out, 256, 256, 2, x);
    // 9. B = LN2(out)
    k_ln2<<<TOT, 256>>>(out, n2g, n2b);
    // 10. H = gelu(B @ fc1_w + b)
    k_gemm<<<dim3(16, MT), 256>>>(pB, fc1w, fc1b, pH, 256, 1024, 1, nullptr);
    // 11. out += H @ fc2_w + b
    k_gemm<<<dim3(4, MT), 256>>>(pH, fc2w, fc2b, out, 1024, 256, 3, out);
}